// round 7
// baseline (speedup 1.0000x reference)
#include <cuda_runtime.h>
#include <cstdint>

// Problem constants
#define T_STEPS 1024
#define B_TOT   256
#define I_DIM   64
#define H_DIM   256
#define O_DIM   16
#define K_TOT   320      // H_DIM + I_DIM
#define NB      2        // batches per CTA
#define N_CTA   128      // 128 * 2 = 256 batches, one CTA per SM
#define NTHR    1024     // thread = (row 0..255, lb 0..1, khalf 0..1)

#define X_SMEM_BYTES (T_STEPS * NB * I_DIM)   // 131072 = 128KB

// Scratch (device globals: no allocation allowed)
__device__ int8_t g_Wcat[H_DIM * K_TOT];   // [h_out][k] int4 values in int8 (-8..7)
__device__ int8_t g_wo[O_DIM * H_DIM];     // [o][k]     int4 values in int8
__device__ float  g_b128[H_DIM];           // 128 * b[n]

// ---------------------------------------------------------------------------
// Prep: quantize weights & bias.  quantize(w,4) -> clip(rint(w*8), -8, 7)
// ---------------------------------------------------------------------------
__global__ void prep_weights(const float* __restrict__ Wi,
                             const float* __restrict__ Wr,
                             const float* __restrict__ Wo,
                             const float* __restrict__ b) {
    int i = blockIdx.x * blockDim.x + threadIdx.x;
    const int NW = H_DIM * K_TOT;           // 81920
    const int NO = O_DIM * H_DIM;           // 4096
    if (i < NW) {
        int n = i / K_TOT, k = i % K_TOT;
        float v = (k < H_DIM) ? Wr[n * H_DIM + k] : Wi[n * I_DIM + (k - H_DIM)];
        int q = __float2int_rn(v * 8.0f);
        q = max(-8, min(7, q));
        g_Wcat[i] = (int8_t)q;
    } else if (i < NW + NO) {
        int j = i - NW;
        int q = __float2int_rn(Wo[j] * 8.0f);
        q = max(-8, min(7, q));
        g_wo[j] = (int8_t)q;
    } else if (i < NW + NO + H_DIM) {
        int n = i - (NW + NO);
        g_b128[n] = 128.0f * b[n];
    }
}

// ---------------------------------------------------------------------------
// One recurrence step (half-dot per thread, shfl-reduced pair).
//   pA: this lane's h-region base  (&hx[buf][lb][half*160], 6 uint4 used)
//   xp: x_t base for this lb       (used when half==1)
//   Exact integer arithmetic end-to-end; epilogue matches reference RN path.
// ---------------------------------------------------------------------------
__device__ __forceinline__ void step_one(const uint4* __restrict__ pA,
                                         const uint4* __restrict__ xp,
                                         int half,
                                         const uint4 (&w)[10],
                                         float b128r,
                                         int8_t* hdst) {
    // half0: pB = pA+6 -> h[96:160).  half1: pB = x[0:64).
    const uint4* pB = half ? xp : (pA + 6);

    int a0 = 0, a1 = 0;
#pragma unroll
    for (int j = 0; j < 6; j += 2) {
        uint4 h0 = pA[j];
        uint4 h1 = pA[j + 1];
        a0 = __dp4a((int)h0.x, (int)w[j].x, a0);
        a1 = __dp4a((int)h1.x, (int)w[j + 1].x, a1);
        a0 = __dp4a((int)h0.y, (int)w[j].y, a0);
        a1 = __dp4a((int)h1.y, (int)w[j + 1].y, a1);
        a0 = __dp4a((int)h0.z, (int)w[j].z, a0);
        a1 = __dp4a((int)h1.z, (int)w[j + 1].z, a1);
        a0 = __dp4a((int)h0.w, (int)w[j].w, a0);
        a1 = __dp4a((int)h1.w, (int)w[j + 1].w, a1);
    }
#pragma unroll
    for (int j = 0; j < 4; j += 2) {
        uint4 h0 = pB[j];
        uint4 h1 = pB[j + 1];
        a0 = __dp4a((int)h0.x, (int)w[6 + j].x, a0);
        a1 = __dp4a((int)h1.x, (int)w[7 + j].x, a1);
        a0 = __dp4a((int)h0.y, (int)w[6 + j].y, a0);
        a1 = __dp4a((int)h1.y, (int)w[7 + j].y, a1);
        a0 = __dp4a((int)h0.z, (int)w[6 + j].z, a0);
        a1 = __dp4a((int)h1.z, (int)w[7 + j].z, a1);
        a0 = __dp4a((int)h0.w, (int)w[6 + j].w, a0);
        a1 = __dp4a((int)h1.w, (int)w[7 + j].w, a1);
    }
    int part = a0 + a1;
    int zi = part + __shfl_xor_sync(0xffffffffu, part, 16);   // pair lanes: same (row,lb)

    // Epilogue: h_new = clip(rint(sign(z) * relu(|z|+b) * 128), -128, 127)
    float fz = (float)zi;                        // exact (|zi| < 2^20)
    float tt = fmaf(fabsf(fz), 0.125f, b128r);   // |zi|/8 + 128b (single RN, matches ref)
    tt = fmaxf(tt, 0.0f);                        // relu
    float v = copysignf(tt, fz);                 // sign(z)*m*128
    int r = __float2int_rn(v);                   // round half-even
    if (zi == 0) r = 0;                          // jnp.sign(0) == 0
    r = max(-128, min(127, r));
    if (!half) *hdst = (int8_t)r;                // one writer per (row,lb)
    __syncthreads();                             // single barrier per step
}

// ---------------------------------------------------------------------------
// Recurrent kernel: 128 CTAs (one per SM) x 2 batches, 1024 threads.
// Each dot product split across a lane pair (K-halves) -> 8 warps/SMSP for
// latency hiding; weights register-resident (10 uint4 per thread).
// ---------------------------------------------------------------------------
__global__ __launch_bounds__(NTHR, 1) void rnn_kernel(const float* __restrict__ inp,
                                                      float* __restrict__ out) {
    extern __shared__ __align__(16) int8_t xs[];        // [t][lb][64] int8, 128KB
    __shared__ __align__(16) int8_t hx[2][NB][256];     // ping-pong h (int8 *128)

    const int tid   = threadIdx.x;
    const int half  = (tid >> 4) & 1;                   // K-half (lane bit 4)
    const int rowlb = (tid & 15) | ((tid >> 5) << 4);   // 0..511
    const int row   = rowlb & 255;
    const int lb    = rowlb >> 8;
    const int cta   = blockIdx.x;

    // This lane's weight half: 160 bytes = 10 uint4
    uint4 w[10];
    {
        const uint4* wp = (const uint4*)(g_Wcat + row * K_TOT + half * 160);
#pragma unroll
        for (int i = 0; i < 10; i++) w[i] = wp[i];
    }
    const float b128r = g_b128[row];

    // --- Quantize this CTA's input slice into smem: [t][lb][i] ---
    {
        const float4* ib = (const float4*)(inp + (size_t)(cta * NB) * (T_STEPS * I_DIM));
        const int NV = (NB * T_STEPS * I_DIM) / 4;     // 32768 float4 groups
#pragma unroll 4
        for (int v = tid; v < NV; v += NTHR) {
            float4 f4 = ib[v];
            int f = v * 4;                              // flat: lb*65536 + t*64 + i
            int l  = f >> 16;
            int t  = (f >> 6) & (T_STEPS - 1);
            int i0 = f & 63;
            int q0 = max(-128, min(127, __float2int_rn(f4.x * 128.0f)));
            int q1 = max(-128, min(127, __float2int_rn(f4.y * 128.0f)));
            int q2 = max(-128, min(127, __float2int_rn(f4.z * 128.0f)));
            int q3 = max(-128, min(127, __float2int_rn(f4.w * 128.0f)));
            unsigned pk = (q0 & 255) | ((q1 & 255) << 8) | ((q2 & 255) << 16) | ((q3 & 255) << 24);
            *(unsigned*)(xs + t * (NB * I_DIM) + l * I_DIM + i0) = pk;
        }
    }
    // zero both h buffers (h0 = 0): 1KB = 64 uint4
    if (tid < 64) ((uint4*)hx)[tid] = make_uint4(0u, 0u, 0u, 0u);
    __syncthreads();

    // Loop-invariant bases
    const uint4* pA0 = (const uint4*)(&hx[0][lb][half * 160]);
    const uint4* pA1 = (const uint4*)(&hx[1][lb][half * 160]);
    int8_t* hd0 = &hx[0][lb][row];
    int8_t* hd1 = &hx[1][lb][row];
    const uint4* xp = (const uint4*)(xs + lb * I_DIM);   // +8 uint4 (128B) per step

    for (int t = 0; t < T_STEPS; t += 2) {
        step_one(pA0, xp, half, w, b128r, hd1);   // reads hx0, writes hx1
        xp += 8;
        step_one(pA1, xp, half, w, b128r, hd0);   // reads hx1, writes hx0
        xp += 8;
    }
    // final h is in hx[0]

    // --- Output head: out[b][o] = (h_last . wo_q) / 1024  (exact in fp32) ---
    if (tid < NB * O_DIM) {
        int bb = tid >> 4;   // local batch
        int o  = tid & 15;
        const uint4* hr = (const uint4*)(&hx[0][bb][0]);
        const uint4* wo = (const uint4*)(g_wo + o * H_DIM);
        int acc = 0;
#pragma unroll
        for (int k = 0; k < 16; k++) {
            uint4 hv = hr[k], wv = wo[k];
            acc = __dp4a((int)hv.x, (int)wv.x, acc);
            acc = __dp4a((int)hv.y, (int)wv.y, acc);
            acc = __dp4a((int)hv.z, (int)wv.z, acc);
            acc = __dp4a((int)hv.w, (int)wv.w, acc);
        }
        out[(cta * NB + bb) * O_DIM + o] = (float)acc * (1.0f / 1024.0f);
    }
}

// ---------------------------------------------------------------------------
// Launch
// ---------------------------------------------------------------------------
extern "C" void kernel_launch(void* const* d_in, const int* in_sizes, int n_in,
                              void* d_out, int out_size) {
    const float* inp = (const float*)d_in[0];   // [256,1024,64]
    const float* Wi  = (const float*)d_in[1];   // [256,64]
    const float* Wr  = (const float*)d_in[2];   // [256,256]
    const float* Wo  = (const float*)d_in[3];   // [16,256]
    const float* b   = (const float*)d_in[4];   // [256]
    float* out = (float*)d_out;                 // [256,16]

    // Host-side attribute set (idempotent, not a stream op, not an allocation).
    cudaFuncSetAttribute(rnn_kernel, cudaFuncAttributeMaxDynamicSharedMemorySize,
                         X_SMEM_BYTES);

    const int total_w = H_DIM * K_TOT + O_DIM * H_DIM + H_DIM;
    prep_weights<<<(total_w + 255) / 256, 256>>>(Wi, Wr, Wo, b);
    rnn_kernel<<<N_CTA, NTHR, X_SMEM_BYTES>>>(inp, out);
}

// round 8
// speedup vs baseline: 1.2028x; 1.2028x over previous
#include <cuda_runtime.h>
#include <cstdint>

// Problem constants
#define T_STEPS 1024
#define B_TOT   256
#define I_DIM   64
#define H_DIM   256
#define O_DIM   16
#define K_TOT   320      // H_DIM + I_DIM
#define N_CTA   256      // one batch per CTA, 2 CTAs per SM
#define NTHR    256      // thread = h_row

#define X_SMEM_BYTES (T_STEPS * I_DIM)   // 65536 = 64KB per CTA (its batch's x)

// Scratch (device globals: no allocation allowed)
__device__ int8_t g_Wcat[H_DIM * K_TOT];   // [h_out][k] int4 values in int8 (-8..7)
__device__ int8_t g_wo[O_DIM * H_DIM];     // [o][k]     int4 values in int8
__device__ float  g_b128[H_DIM];           // 128 * b[n]

// ---------------------------------------------------------------------------
// Prep: quantize weights & bias.  quantize(w,4) -> clip(rint(w*8), -8, 7)
// ---------------------------------------------------------------------------
__global__ void prep_weights(const float* __restrict__ Wi,
                             const float* __restrict__ Wr,
                             const float* __restrict__ Wo,
                             const float* __restrict__ b) {
    int i = blockIdx.x * blockDim.x + threadIdx.x;
    const int NW = H_DIM * K_TOT;           // 81920
    const int NO = O_DIM * H_DIM;           // 4096
    if (i < NW) {
        int n = i / K_TOT, k = i % K_TOT;
        float v = (k < H_DIM) ? Wr[n * H_DIM + k] : Wi[n * I_DIM + (k - H_DIM)];
        int q = __float2int_rn(v * 8.0f);
        q = max(-8, min(7, q));
        g_Wcat[i] = (int8_t)q;
    } else if (i < NW + NO) {
        int j = i - NW;
        int q = __float2int_rn(Wo[j] * 8.0f);
        q = max(-8, min(7, q));
        g_wo[j] = (int8_t)q;
    } else if (i < NW + NO + H_DIM) {
        int n = i - (NW + NO);
        g_b128[n] = 128.0f * b[n];
    }
}

// ---------------------------------------------------------------------------
// One recurrence step for one row-thread (full K=320 dot).
//   hp:   current h vector base (16 uint4, broadcast within warp)
//   xp:   x_t base (4 uint4, broadcast)
//   hdst: &hx[next_buf][row]
// Exact integer arithmetic: z = zi/1024 ; m*128 = relu(|zi|/8 + 128*b);
// h_int = rni(sign(zi)*m*128) clamped to [-128,127].
// ---------------------------------------------------------------------------
__device__ __forceinline__ void step_one(const uint4* __restrict__ hp,
                                         const uint4* __restrict__ xp,
                                         const uint4 (&w)[20],
                                         float b128r,
                                         int8_t* hdst) {
    int a0 = 0, a1 = 0;
#pragma unroll
    for (int kk = 0; kk < 16; kk += 2) {
        uint4 h0 = hp[kk];
        uint4 h1 = hp[kk + 1];
        a0 = __dp4a((int)h0.x, (int)w[kk].x, a0);
        a1 = __dp4a((int)h1.x, (int)w[kk + 1].x, a1);
        a0 = __dp4a((int)h0.y, (int)w[kk].y, a0);
        a1 = __dp4a((int)h1.y, (int)w[kk + 1].y, a1);
        a0 = __dp4a((int)h0.z, (int)w[kk].z, a0);
        a1 = __dp4a((int)h1.z, (int)w[kk + 1].z, a1);
        a0 = __dp4a((int)h0.w, (int)w[kk].w, a0);
        a1 = __dp4a((int)h1.w, (int)w[kk + 1].w, a1);
    }
    {
        uint4 x0 = xp[0];
        uint4 x1 = xp[1];
        uint4 x2 = xp[2];
        uint4 x3 = xp[3];
        a0 = __dp4a((int)x0.x, (int)w[16].x, a0);
        a1 = __dp4a((int)x1.x, (int)w[17].x, a1);
        a0 = __dp4a((int)x0.y, (int)w[16].y, a0);
        a1 = __dp4a((int)x1.y, (int)w[17].y, a1);
        a0 = __dp4a((int)x0.z, (int)w[16].z, a0);
        a1 = __dp4a((int)x1.z, (int)w[17].z, a1);
        a0 = __dp4a((int)x0.w, (int)w[16].w, a0);
        a1 = __dp4a((int)x1.w, (int)w[17].w, a1);
        a0 = __dp4a((int)x2.x, (int)w[18].x, a0);
        a1 = __dp4a((int)x3.x, (int)w[19].x, a1);
        a0 = __dp4a((int)x2.y, (int)w[18].y, a0);
        a1 = __dp4a((int)x3.y, (int)w[19].y, a1);
        a0 = __dp4a((int)x2.z, (int)w[18].z, a0);
        a1 = __dp4a((int)x3.z, (int)w[19].z, a1);
        a0 = __dp4a((int)x2.w, (int)w[18].w, a0);
        a1 = __dp4a((int)x3.w, (int)w[19].w, a1);
    }
    int zi = a0 + a1;

    float fz = (float)zi;                        // exact (|zi| < 2^20)
    float tt = fmaf(fabsf(fz), 0.125f, b128r);   // |zi|/8 + 128b (single RN, matches ref)
    tt = fmaxf(tt, 0.0f);                        // relu
    float v = copysignf(tt, fz);                 // sign(z)*m*128
    int r = __float2int_rn(v);                   // round half-even
    if (zi == 0) r = 0;                          // jnp.sign(0) == 0
    r = max(-128, min(127, r));
    *hdst = (int8_t)r;
    __syncthreads();                             // per-CTA barrier (independent across the 2 CTAs/SM)
}

// ---------------------------------------------------------------------------
// Recurrent kernel: 256 CTAs x 256 threads, ONE batch per CTA, 2 CTAs per SM.
// The two co-resident CTAs sync independently, so one CTA's dp4a bursts cover
// the other's LDS-latency/epilogue/barrier phases.
// ---------------------------------------------------------------------------
__global__ __launch_bounds__(NTHR, 2) void rnn_kernel(const float* __restrict__ inp,
                                                      float* __restrict__ out) {
    extern __shared__ __align__(16) int8_t xs[];   // [t][64] int8, 64KB
    __shared__ __align__(16) int8_t hx[2][256];    // ping-pong h (int8 *128)

    const int tid = threadIdx.x;       // == row
    const int cta = blockIdx.x;        // == batch index

    // Weight row resident in registers (80 bytes = 20 uint4)
    uint4 w[20];
    {
        const uint4* wp = (const uint4*)(g_Wcat + tid * K_TOT);
#pragma unroll
        for (int i = 0; i < 20; i++) w[i] = wp[i];
    }
    const float b128r = g_b128[tid];

    // --- Quantize this CTA's batch input into smem: [t][i] ---
    {
        const float4* ib = (const float4*)(inp + (size_t)cta * (T_STEPS * I_DIM));
        const int NV = (T_STEPS * I_DIM) / 4;      // 16384 float4 groups
#pragma unroll 4
        for (int v = tid; v < NV; v += NTHR) {
            float4 f4 = ib[v];
            int q0 = max(-128, min(127, __float2int_rn(f4.x * 128.0f)));
            int q1 = max(-128, min(127, __float2int_rn(f4.y * 128.0f)));
            int q2 = max(-128, min(127, __float2int_rn(f4.z * 128.0f)));
            int q3 = max(-128, min(127, __float2int_rn(f4.w * 128.0f)));
            unsigned pk = (q0 & 255) | ((q1 & 255) << 8) | ((q2 & 255) << 16) | ((q3 & 255) << 24);
            ((unsigned*)xs)[v] = pk;               // same flat layout as input slice
        }
    }
    // zero both h buffers (h0 = 0): 512B = 32 uint4
    if (tid < 32) ((uint4*)hx)[tid] = make_uint4(0u, 0u, 0u, 0u);
    __syncthreads();

    // Loop-invariant bases
    const uint4* hb0 = (const uint4*)(&hx[0][0]);
    const uint4* hb1 = (const uint4*)(&hx[1][0]);
    int8_t* hd0 = &hx[0][tid];
    int8_t* hd1 = &hx[1][tid];
    const uint4* xp = (const uint4*)xs;            // +4 uint4 (64B) per step

    for (int t = 0; t < T_STEPS; t += 2) {
        step_one(hb0, xp,     w, b128r, hd1);      // reads hx0, writes hx1
        step_one(hb1, xp + 4, w, b128r, hd0);      // reads hx1, writes hx0
        xp += 8;
    }
    // final h is in hx[0]

    // --- Output head: out[cta][o] = (h_last . wo_q) / 1024  (exact in fp32) ---
    if (tid < O_DIM) {
        const uint4* hr = (const uint4*)(&hx[0][0]);
        const uint4* wo = (const uint4*)(g_wo + tid * H_DIM);
        int acc = 0;
#pragma unroll
        for (int k = 0; k < 16; k++) {
            uint4 hv = hr[k], wv = wo[k];
            acc = __dp4a((int)hv.x, (int)wv.x, acc);
            acc = __dp4a((int)hv.y, (int)wv.y, acc);
            acc = __dp4a((int)hv.z, (int)wv.z, acc);
            acc = __dp4a((int)hv.w, (int)wv.w, acc);
        }
        out[cta * O_DIM + tid] = (float)acc * (1.0f / 1024.0f);
    }
}

// ---------------------------------------------------------------------------
// Launch
// ---------------------------------------------------------------------------
extern "C" void kernel_launch(void* const* d_in, const int* in_sizes, int n_in,
                              void* d_out, int out_size) {
    const float* inp = (const float*)d_in[0];   // [256,1024,64]
    const float* Wi  = (const float*)d_in[1];   // [256,64]
    const float* Wr  = (const float*)d_in[2];   // [256,256]
    const float* Wo  = (const float*)d_in[3];   // [16,256]
    const float* b   = (const float*)d_in[4];   // [256]
    float* out = (float*)d_out;                 // [256,16]

    // Host-side attribute set (idempotent, not a stream op, not an allocation).
    cudaFuncSetAttribute(rnn_kernel, cudaFuncAttributeMaxDynamicSharedMemorySize,
                         X_SMEM_BYTES);

    const int total_w = H_DIM * K_TOT + O_DIM * H_DIM + H_DIM;
    prep_weights<<<(total_w + 255) / 256, 256>>>(Wi, Wr, Wo, b);
    rnn_kernel<<<N_CTA, NTHR, X_SMEM_BYTES>>>(inp, out);
}

// round 9
// speedup vs baseline: 1.3254x; 1.1019x over previous
#include <cuda_runtime.h>
#include <cstdint>

// Problem constants
#define T_STEPS 1024
#define B_TOT   256
#define I_DIM   64
#define H_DIM   256
#define O_DIM   16
#define K_TOT   320      // H_DIM + I_DIM
#define N_CTA   256      // one batch per CTA, 2 CTAs per SM
#define NTHR    128      // thread = row pair {2*tid, 2*tid+1}

#define X_SMEM_BYTES (T_STEPS * I_DIM)   // 65536 = 64KB per CTA (its batch's x)

// Scratch (device globals: no allocation allowed)
__device__ int8_t g_Wcat[H_DIM * K_TOT];   // [h_out][k] int4 values in int8 (-8..7)
__device__ int8_t g_wo[O_DIM * H_DIM];     // [o][k]     int4 values in int8
__device__ float  g_b128[H_DIM];           // 128 * b[n]

// ---------------------------------------------------------------------------
// Prep: quantize weights & bias.  quantize(w,4) -> clip(rint(w*8), -8, 7)
// ---------------------------------------------------------------------------
__global__ void prep_weights(const float* __restrict__ Wi,
                             const float* __restrict__ Wr,
                             const float* __restrict__ Wo,
                             const float* __restrict__ b) {
    int i = blockIdx.x * blockDim.x + threadIdx.x;
    const int NW = H_DIM * K_TOT;           // 81920
    const int NO = O_DIM * H_DIM;           // 4096
    if (i < NW) {
        int n = i / K_TOT, k = i % K_TOT;
        float v = (k < H_DIM) ? Wr[n * H_DIM + k] : Wi[n * I_DIM + (k - H_DIM)];
        int q = __float2int_rn(v * 8.0f);
        q = max(-8, min(7, q));
        g_Wcat[i] = (int8_t)q;
    } else if (i < NW + NO) {
        int j = i - NW;
        int q = __float2int_rn(Wo[j] * 8.0f);
        q = max(-8, min(7, q));
        g_wo[j] = (int8_t)q;
    } else if (i < NW + NO + H_DIM) {
        int n = i - (NW + NO);
        g_b128[n] = 128.0f * b[n];
    }
}

// 16 dp4a: one 16-byte operand chunk against one weight chunk, two chains
#define DP16(OP, WA, WB, A0, A1)                   \
    A0 = __dp4a((int)(OP).x, (int)(WA).x, A0);     \
    A1 = __dp4a((int)(OP).x, (int)(WB).x, A1);     \
    A0 = __dp4a((int)(OP).y, (int)(WA).y, A0);     \
    A1 = __dp4a((int)(OP).y, (int)(WB).y, A1);     \
    A0 = __dp4a((int)(OP).z, (int)(WA).z, A0);     \
    A1 = __dp4a((int)(OP).z, (int)(WB).z, A1);     \
    A0 = __dp4a((int)(OP).w, (int)(WA).w, A0);     \
    A1 = __dp4a((int)(OP).w, (int)(WB).w, A1);

// ---------------------------------------------------------------------------
// Exact epilogue: h_new = clip(rint(sign(z) * relu(|z|+b) * 128), -128, 127)
//   z = zi/1024 -> target = sign(zi)*relu(|zi|/8 + 128*b), rni, clamp.
// ---------------------------------------------------------------------------
__device__ __forceinline__ int epilogue(int zi, float b128r) {
    float fz = (float)zi;                        // exact (|zi| < 2^20)
    float tt = fmaf(fabsf(fz), 0.125f, b128r);   // |zi|/8 + 128b (single RN, matches ref)
    tt = fmaxf(tt, 0.0f);                        // relu
    float v = copysignf(tt, fz);                 // sign(z)*m*128
    int r = __float2int_rn(v);                   // round half-even
    if (zi == 0) r = 0;                          // jnp.sign(0) == 0
    return max(-128, min(127, r));
}

// ---------------------------------------------------------------------------
// One recurrence step: thread computes rows {2*tid, 2*tid+1} of h_next.
//   hp: current h vector (16 uint4), xp: x_t (4 uint4) — both warp-broadcast.
//   Operand loads batched 10-wide so LDS latency is covered by dp4a bursts.
// ---------------------------------------------------------------------------
__device__ __forceinline__ void step2(const uint4* __restrict__ hp,
                                      const uint4* __restrict__ xp,
                                      const uint4 (&w0)[20],
                                      const uint4 (&w1)[20],
                                      float bA, float bB,
                                      uint16_t* hdst) {
    int r0a = 0, r0b = 0, r1a = 0, r1b = 0;

    // Half 1: operand chunks 0..9 (h bytes 0..159)
    {
        uint4 o0 = hp[0], o1 = hp[1], o2 = hp[2], o3 = hp[3], o4 = hp[4];
        uint4 o5 = hp[5], o6 = hp[6], o7 = hp[7], o8 = hp[8], o9 = hp[9];
        DP16(o0, w0[0], w1[0], r0a, r1a)
        DP16(o1, w0[1], w1[1], r0b, r1b)
        DP16(o2, w0[2], w1[2], r0a, r1a)
        DP16(o3, w0[3], w1[3], r0b, r1b)
        DP16(o4, w0[4], w1[4], r0a, r1a)
        DP16(o5, w0[5], w1[5], r0b, r1b)
        DP16(o6, w0[6], w1[6], r0a, r1a)
        DP16(o7, w0[7], w1[7], r0b, r1b)
        DP16(o8, w0[8], w1[8], r0a, r1a)
        DP16(o9, w0[9], w1[9], r0b, r1b)
    }
    // Half 2: operand chunks 10..15 (h bytes 160..255) + x chunks 0..3
    {
        uint4 o0 = hp[10], o1 = hp[11], o2 = hp[12], o3 = hp[13], o4 = hp[14];
        uint4 o5 = hp[15], o6 = xp[0], o7 = xp[1], o8 = xp[2], o9 = xp[3];
        DP16(o0, w0[10], w1[10], r0a, r1a)
        DP16(o1, w0[11], w1[11], r0b, r1b)
        DP16(o2, w0[12], w1[12], r0a, r1a)
        DP16(o3, w0[13], w1[13], r0b, r1b)
        DP16(o4, w0[14], w1[14], r0a, r1a)
        DP16(o5, w0[15], w1[15], r0b, r1b)
        DP16(o6, w0[16], w1[16], r0a, r1a)
        DP16(o7, w0[17], w1[17], r0b, r1b)
        DP16(o8, w0[18], w1[18], r0a, r1a)
        DP16(o9, w0[19], w1[19], r0b, r1b)
    }
    int z0 = r0a + r0b;
    int z1 = r1a + r1b;
    int c0 = epilogue(z0, bA);
    int c1 = epilogue(z1, bB);
    *hdst = (uint16_t)((c0 & 255) | ((c1 & 255) << 8));  // rows 2t, 2t+1 adjacent
    __syncthreads();                                      // per-CTA barrier
}

// ---------------------------------------------------------------------------
// Recurrent kernel: 256 CTAs x 128 threads, ONE batch per CTA, 2 CTAs/SM.
// Thread owns 2 adjacent rows: halves LDS wavefronts per MAC, and the big
// register budget (256/thread) lets loads batch 10-wide ahead of the dp4a.
// ---------------------------------------------------------------------------
__global__ __launch_bounds__(NTHR, 2) void rnn_kernel(const float* __restrict__ inp,
                                                      float* __restrict__ out) {
    extern __shared__ __align__(16) int8_t xs[];   // [t][64] int8, 64KB
    __shared__ __align__(16) int8_t hx[2][256];    // ping-pong h (int8 *128)

    const int tid = threadIdx.x;       // row pair index
    const int cta = blockIdx.x;        // batch index
    const int rA  = 2 * tid;
    const int rB  = 2 * tid + 1;

    // Two weight rows resident in registers (2 x 80 bytes = 40 uint4)
    uint4 w0[20], w1[20];
    {
        const uint4* p0 = (const uint4*)(g_Wcat + rA * K_TOT);
        const uint4* p1 = (const uint4*)(g_Wcat + rB * K_TOT);
#pragma unroll
        for (int i = 0; i < 20; i++) { w0[i] = p0[i]; w1[i] = p1[i]; }
    }
    const float bA = g_b128[rA];
    const float bB = g_b128[rB];

    // --- Quantize this CTA's batch input into smem: [t][i] ---
    {
        const float4* ib = (const float4*)(inp + (size_t)cta * (T_STEPS * I_DIM));
        const int NV = (T_STEPS * I_DIM) / 4;      // 16384 float4 groups
#pragma unroll 4
        for (int v = tid; v < NV; v += NTHR) {
            float4 f4 = ib[v];
            int q0 = max(-128, min(127, __float2int_rn(f4.x * 128.0f)));
            int q1 = max(-128, min(127, __float2int_rn(f4.y * 128.0f)));
            int q2 = max(-128, min(127, __float2int_rn(f4.z * 128.0f)));
            int q3 = max(-128, min(127, __float2int_rn(f4.w * 128.0f)));
            unsigned pk = (q0 & 255) | ((q1 & 255) << 8) | ((q2 & 255) << 16) | ((q3 & 255) << 24);
            ((unsigned*)xs)[v] = pk;
        }
    }
    // zero both h buffers (h0 = 0): 512B = 32 uint4
    if (tid < 32) ((uint4*)hx)[tid] = make_uint4(0u, 0u, 0u, 0u);
    __syncthreads();

    // Loop-invariant bases
    const uint4* hb0 = (const uint4*)(&hx[0][0]);
    const uint4* hb1 = (const uint4*)(&hx[1][0]);
    uint16_t* hd0 = (uint16_t*)(&hx[0][rA]);
    uint16_t* hd1 = (uint16_t*)(&hx[1][rA]);
    const uint4* xp = (const uint4*)xs;            // +4 uint4 (64B) per step

    for (int t = 0; t < T_STEPS; t += 2) {
        step2(hb0, xp,     w0, w1, bA, bB, hd1);   // reads hx0, writes hx1
        step2(hb1, xp + 4, w0, w1, bA, bB, hd0);   // reads hx1, writes hx0
        xp += 8;
    }
    // final h is in hx[0]

    // --- Output head: out[cta][o] = (h_last . wo_q) / 1024  (exact in fp32) ---
    if (tid < O_DIM) {
        const uint4* hr = (const uint4*)(&hx[0][0]);
        const uint4* wo = (const uint4*)(g_wo + tid * H_DIM);
        int acc = 0;
#pragma unroll
        for (int k = 0; k < 16; k++) {
            uint4 hv = hr[k], wv = wo[k];
            acc = __dp4a((int)hv.x, (int)wv.x, acc);
            acc = __dp4a((int)hv.y, (int)wv.y, acc);
            acc = __dp4a((int)hv.z, (int)wv.z, acc);
            acc = __dp4a((int)hv.w, (int)wv.w, acc);
        }
        out[cta * O_DIM + tid] = (float)acc * (1.0f / 1024.0f);
    }
}

// ---------------------------------------------------------------------------
// Launch
// ---------------------------------------------------------------------------
extern "C" void kernel_launch(void* const* d_in, const int* in_sizes, int n_in,
                              void* d_out, int out_size) {
    const float* inp = (const float*)d_in[0];   // [256,1024,64]
    const float* Wi  = (const float*)d_in[1];   // [256,64]
    const float* Wr  = (const float*)d_in[2];   // [256,256]
    const float* Wo  = (const float*)d_in[3];   // [16,256]
    const float* b   = (const float*)d_in[4];   // [256]
    float* out = (float*)d_out;                 // [256,16]

    // Host-side attribute set (idempotent, not a stream op, not an allocation).
    cudaFuncSetAttribute(rnn_kernel, cudaFuncAttributeMaxDynamicSharedMemorySize,
                         X_SMEM_BYTES);

    const int total_w = H_DIM * K_TOT + O_DIM * H_DIM + H_DIM;
    prep_weights<<<(total_w + 255) / 256, 256>>>(Wi, Wr, Wo, b);
    rnn_kernel<<<N_CTA, NTHR, X_SMEM_BYTES>>>(inp, out);
}